// round 5
// baseline (speedup 1.0000x reference)
#include <cuda_runtime.h>

#define BINS 10
#define TPB  256
#define BPSM 4
#define GRID (152 * BPSM)   // one wave on GB300 (152 SMs)

// Global scratch (allocation-free: __device__ globals, zero-initialized at load;
// the last block re-zeros them each run so graph replays stay deterministic).
__device__ double       g_cnt[BINS];
__device__ double       g_sum[BINS];
__device__ unsigned int g_done;

__device__ __forceinline__ float rcp_fast(float x) { float r; asm("rcp.approx.f32 %0, %1;" : "=f"(r) : "f"(x)); return r; }
__device__ __forceinline__ float lg2_fast(float x) { float r; asm("lg2.approx.f32 %0, %1;" : "=f"(r) : "f"(x)); return r; }
__device__ __forceinline__ float ex2_fast(float x) { float r; asm("ex2.approx.f32 %0, %1;" : "=f"(r) : "f"(x)); return r; }

// s = (y==1) ? -x : x (sign fold via mask). Key: |s| = |x|, so the heavy math
// (EX2/RCP/LG2) depends only on |x|; sign picks bin half and the max(s,0) term.
//   e = exp(-|x|); d = 1+e; sigma = 1/d
//   pos (s>=0): g = sigma          -> bin = trunc(9.9999*sigma)
//   neg (s<0) : g = 1 - sigma      -> bin = trunc(9.9999 - 9.9999*sigma)
//   bce = max(s,0) + ln(d) = (pos ? |x| : 0) + lg2(d)*ln2
__device__ __forceinline__ void ghm_elem(float x, unsigned mask, float2* hcol)
{
    int   sx = __float_as_int(x) ^ (int)mask;
    float ax = fabsf(x);
    float e  = ex2_fast(ax * -1.4426950408889634f);
    float d  = 1.0f + e;
    float u  = rcp_fast(d) * 9.9999f;          // in [4.99995, 9.9999)
    bool pos = (sx >= 0);
    float us = pos ? u : (9.9999f - u);
    int  bin = (int)us;                        // in [0, 9], no clamp needed
    float m  = pos ? ax : 0.0f;
    float bce = fmaf(lg2_fast(d), 0.69314718055994531f, m);
    float2* p = hcol + bin * TPB;              // bank = tid (mod 32): conflict-free
    float2 h = *p;
    h.x += 1.0f;
    h.y += bce;
    *p = h;
}

__global__ void __launch_bounds__(TPB, BPSM)
ghm_fused(const float4* __restrict__ x4,
          const int4*   __restrict__ t4,
          int nquads, int nrows,
          const float* __restrict__ xs,
          const int*   __restrict__ ts,
          float* __restrict__ out)
{
    // Two privatized histograms (even/odd element slots) -> two independent
    // smem RMW chains per iteration.
    __shared__ float2 hist[2][BINS][TPB];
    __shared__ int    s_last;
    const int tid = threadIdx.x;
    float2* hc0 = &hist[0][0][tid];
    float2* hc1 = &hist[1][0][tid];
#pragma unroll
    for (int b = 0; b < BINS; b++) {
        hist[0][b][tid] = make_float2(0.0f, 0.0f);
        hist[1][b][tid] = make_float2(0.0f, 0.0f);
    }
    __syncthreads();

    // Software-pipelined grid-stride loop: prefetch iteration i+1 while
    // processing iteration i, so DRAM latency overlaps the compute+RMW body.
    const int stride = GRID * TPB;
    int i = blockIdx.x * TPB + tid;
    bool valid = (i < nquads);
    float4 xa, xb; int4 tv;
    if (valid) {
        xa = __ldcs(&x4[2 * i]);
        xb = __ldcs(&x4[2 * i + 1]);
        tv = __ldcs(&t4[i]);
    }
    while (valid) {
        int inext = i + stride;
        bool vnext = (inext < nquads);
        float4 nxa, nxb; int4 ntv;
        if (vnext) {
            nxa = __ldcs(&x4[2 * inext]);
            nxb = __ldcs(&x4[2 * inext + 1]);
            ntv = __ldcs(&t4[inext]);
        }

        // Row sign masks: class1 mask = t<<31, class0 mask = that ^ signbit.
        unsigned ma1 = ((unsigned)tv.x) << 31, ma0 = ma1 ^ 0x80000000u;
        unsigned mb1 = ((unsigned)tv.y) << 31, mb0 = mb1 ^ 0x80000000u;
        unsigned mc1 = ((unsigned)tv.z) << 31, mc0 = mc1 ^ 0x80000000u;
        unsigned md1 = ((unsigned)tv.w) << 31, md0 = md1 ^ 0x80000000u;

        ghm_elem(xa.x, ma0, hc0);
        ghm_elem(xa.y, ma1, hc1);
        ghm_elem(xa.z, mb0, hc0);
        ghm_elem(xa.w, mb1, hc1);
        ghm_elem(xb.x, mc0, hc0);
        ghm_elem(xb.y, mc1, hc1);
        ghm_elem(xb.z, md0, hc0);
        ghm_elem(xb.w, md1, hc1);

        xa = nxa; xb = nxb; tv = ntv;
        i = inext; valid = vnext;
    }

    // Tail rows (nrows % 4 != 0): direct double atomics, block 0 only.
    if (blockIdx.x == 0) {
        int tail0 = nquads * 4;
        for (int rowi = tail0 + tid; rowi < nrows; rowi += TPB) {
            int t = ts[rowi];
            for (int c = 0; c < 2; c++) {
                float x = xs[rowi * 2 + c];
                unsigned mask = ((t == c) ? 0x80000000u : 0u);
                int   sx = __float_as_int(x) ^ (int)mask;
                float ax = fabsf(x);
                float e  = ex2_fast(ax * -1.4426950408889634f);
                float d  = 1.0f + e;
                float u  = rcp_fast(d) * 9.9999f;
                bool pos = (sx >= 0);
                float us = pos ? u : (9.9999f - u);
                int  bin = (int)us;
                float m  = pos ? ax : 0.0f;
                float bce = fmaf(lg2_fast(d), 0.69314718055994531f, m);
                atomicAdd(&g_cnt[bin], 1.0);
                atomicAdd(&g_sum[bin], (double)bce);
            }
        }
    }
    __syncthreads();

    // Fold copy 1 into copy 0, then tree-reduce 256 columns x 10 bins.
#pragma unroll
    for (int b = 0; b < BINS; b++) {
        float2 a = hist[0][b][tid];
        float2 c = hist[1][b][tid];
        hist[0][b][tid] = make_float2(a.x + c.x, a.y + c.y);
    }
    __syncthreads();
    for (int off = TPB / 2; off > 0; off >>= 1) {
        if (tid < off) {
#pragma unroll
            for (int b = 0; b < BINS; b++) {
                float2 a = hist[0][b][tid];
                float2 c = hist[0][b][tid + off];
                hist[0][b][tid] = make_float2(a.x + c.x, a.y + c.y);
            }
        }
        __syncthreads();
    }

    if (tid < BINS) {
        atomicAdd(&g_cnt[tid], (double)hist[0][tid][0].x);
        atomicAdd(&g_sum[tid], (double)hist[0][tid][0].y);
    }
    __syncthreads();

    // Last-block finalize (and reset for the next graph replay).
    if (tid == 0) {
        __threadfence();
        unsigned old = atomicAdd(&g_done, 1u);
        s_last = (old == GRID - 1) ? 1 : 0;
    }
    __syncthreads();

    if (s_last && tid == 0) {
        __threadfence();
        volatile double* vc = g_cnt;
        volatile double* vs = g_sum;
        double cnt[BINS], sum[BINS];
        double nonempty = 0.0;
        for (int b = 0; b < BINS; b++) {
            cnt[b] = vc[b];
            sum[b] = vs[b];
            if (cnt[b] > 0.0) nonempty += 1.0;
        }
        // mean(weight*bce) = (1/N) * sum_b (N/gd_b) * S_b = sum_b S_b / gd_b
        double loss = 0.0;
        for (int b = 0; b < BINS; b++) {
            double gd = cnt[b] * nonempty;
            if (gd < 1e-4) gd = 1e-4;
            loss += sum[b] / gd;
        }
        out[0] = (float)loss;
        for (int b = 0; b < BINS; b++) { vc[b] = 0.0; vs[b] = 0.0; }
        __threadfence();
        g_done = 0u;
    }
}

extern "C" void kernel_launch(void* const* d_in, const int* in_sizes, int n_in,
                              void* d_out, int out_size)
{
    // x: [B,2] float32 (2B elems), target: [B] int32 (B elems) — identify by count.
    const float* x;
    const int*   t;
    int nrows;
    if (in_sizes[0] >= 2 * in_sizes[1]) {
        x = (const float*)d_in[0];
        t = (const int*)d_in[1];
        nrows = in_sizes[1];
    } else {
        x = (const float*)d_in[1];
        t = (const int*)d_in[0];
        nrows = in_sizes[0];
    }
    int nquads = nrows >> 2;

    ghm_fused<<<GRID, TPB>>>((const float4*)x, (const int4*)t, nquads, nrows,
                             x, t, (float*)d_out);
}

// round 6
// speedup vs baseline: 1.0137x; 1.0137x over previous
#include <cuda_runtime.h>

#define BINS 10
#define TPB  256
#define BPSM 5
#define GRID (152 * BPSM)   // one wave on GB300 (152 SMs)

// Global scratch (allocation-free __device__ globals, zero-init at load;
// last block re-zeros them each run so graph replays stay deterministic).
__device__ double       g_cnt[BINS];
__device__ double       g_sum[BINS];
__device__ unsigned int g_done;

__device__ __forceinline__ float rcp_fast(float x) { float r; asm("rcp.approx.f32 %0, %1;" : "=f"(r) : "f"(x)); return r; }
__device__ __forceinline__ float lg2_fast(float x) { float r; asm("lg2.approx.f32 %0, %1;" : "=f"(r) : "f"(x)); return r; }
__device__ __forceinline__ float ex2_fast(float x) { float r; asm("ex2.approx.f32 %0, %1;" : "=f"(r) : "f"(x)); return r; }

__device__ __forceinline__ unsigned smem_off(const void* p)
{
    unsigned a;
    asm("{ .reg .u64 t; cvta.to.shared.u64 t, %1; cvt.u32.u64 %0, t; }"
        : "=r"(a) : "l"(p));
    return a;
}

// One element, fully pinned at PTX level (19 ops):
//   s = x ^ mask  (mask = target-match << 31)
//   e = 2^(-|x|*log2e) = exp(-|x|);  d = 1+e;  u = 9.9999 * rcp(d)
//   us = (s>=0) ? u : 9.9999-u;  bin = trunc(us)  (in [0,9] by construction)
//   bce = max(s,0) + ln2 * lg2(d)
//   hist RMW: float2 at hoff + bin*2048 (bank = tid: conflict-free)
// Constants: 0fBFB8AA3B = -log2(e), 0f411FFF97 = 9.9999f, 0f3F317218 = ln(2)
#define GHM_ELEM(xval, msk, hoff)                                        \
    asm volatile(                                                        \
        "{\n\t"                                                          \
        ".reg .f32 ax,w,e,d,r,u,v,us,s,m,lg,b,h0,h1;\n\t"               \
        ".reg .pred p;\n\t"                                              \
        ".reg .b32 sx,bin,off;\n\t"                                      \
        "xor.b32 sx, %0, %1;\n\t"                                        \
        "abs.f32 ax, %2;\n\t"                                            \
        "mul.f32 w, ax, 0fBFB8AA3B;\n\t"                                 \
        "ex2.approx.f32 e, w;\n\t"                                       \
        "add.f32 d, e, 0f3F800000;\n\t"                                  \
        "rcp.approx.f32 r, d;\n\t"                                       \
        "mul.f32 u, r, 0f411FFF97;\n\t"                                  \
        "sub.f32 v, 0f411FFF97, u;\n\t"                                  \
        "setp.ge.s32 p, sx, 0;\n\t"                                      \
        "selp.f32 us, u, v, p;\n\t"                                      \
        "cvt.rzi.s32.f32 bin, us;\n\t"                                   \
        "mov.b32 s, sx;\n\t"                                             \
        "max.f32 m, s, 0f00000000;\n\t"                                  \
        "lg2.approx.f32 lg, d;\n\t"                                      \
        "fma.rn.f32 b, lg, 0f3F317218, m;\n\t"                           \
        "mad.lo.s32 off, bin, 2048, %3;\n\t"                             \
        "ld.shared.v2.f32 {h0,h1}, [off];\n\t"                           \
        "add.f32 h0, h0, 0f3F800000;\n\t"                                \
        "add.f32 h1, h1, b;\n\t"                                         \
        "st.shared.v2.f32 [off], {h0,h1};\n\t"                           \
        "}\n\t"                                                          \
        :: "r"(__float_as_int(xval)), "r"(msk), "f"(xval), "r"(hoff))

__global__ void __launch_bounds__(TPB, BPSM)
ghm_fused(const float4* __restrict__ x4,
          const int4*   __restrict__ t4,
          int nquads, int nrows,
          const float* __restrict__ xs,
          const int*   __restrict__ ts,
          float* __restrict__ out)
{
    // Two privatized histograms (even/odd element slots) -> two independent
    // smem RMW chains. hist[c][bin][tid], float2 = (count, bce_sum).
    __shared__ float2 hist[2][BINS][TPB];
    __shared__ int    s_last;
    const int tid = threadIdx.x;
#pragma unroll
    for (int b = 0; b < BINS; b++) {
        hist[0][b][tid] = make_float2(0.0f, 0.0f);
        hist[1][b][tid] = make_float2(0.0f, 0.0f);
    }
    __syncthreads();

    const unsigned h0 = smem_off(&hist[0][0][tid]);
    const unsigned h1 = h0 + BINS * TPB * 8;    // hist[1] same tid column

    const int stride = GRID * TPB;
    for (int i = blockIdx.x * TPB + tid; i < nquads; i += stride) {
        float4 xa = __ldcs(&x4[2 * i]);
        float4 xb = __ldcs(&x4[2 * i + 1]);
        int4   tv = __ldcs(&t4[i]);

        // Row sign masks: class1 mask = t<<31, class0 mask = that ^ signbit.
        unsigned ma1 = ((unsigned)tv.x) << 31, ma0 = ma1 ^ 0x80000000u;
        unsigned mb1 = ((unsigned)tv.y) << 31, mb0 = mb1 ^ 0x80000000u;
        unsigned mc1 = ((unsigned)tv.z) << 31, mc0 = mc1 ^ 0x80000000u;
        unsigned md1 = ((unsigned)tv.w) << 31, md0 = md1 ^ 0x80000000u;

        GHM_ELEM(xa.x, ma0, h0);
        GHM_ELEM(xa.y, ma1, h1);
        GHM_ELEM(xa.z, mb0, h0);
        GHM_ELEM(xa.w, mb1, h1);
        GHM_ELEM(xb.x, mc0, h0);
        GHM_ELEM(xb.y, mc1, h1);
        GHM_ELEM(xb.z, md0, h0);
        GHM_ELEM(xb.w, md1, h1);
    }

    // Tail rows (nrows % 4 != 0): direct double atomics, block 0 only.
    if (blockIdx.x == 0) {
        int tail0 = nquads * 4;
        for (int rowi = tail0 + tid; rowi < nrows; rowi += TPB) {
            int t = ts[rowi];
            for (int c = 0; c < 2; c++) {
                float x = xs[rowi * 2 + c];
                unsigned mask = ((t == c) ? 0x80000000u : 0u);
                int   sx = __float_as_int(x) ^ (int)mask;
                float ax = fabsf(x);
                float e  = ex2_fast(ax * -1.4426950408889634f);
                float d  = 1.0f + e;
                float u  = rcp_fast(d) * 9.9999f;
                bool pos = (sx >= 0);
                float us = pos ? u : (9.9999f - u);
                int  bin = (int)us;
                float m  = pos ? ax : 0.0f;
                float bce = fmaf(lg2_fast(d), 0.69314718055994531f, m);
                atomicAdd(&g_cnt[bin], 1.0);
                atomicAdd(&g_sum[bin], (double)bce);
            }
        }
    }
    __syncthreads();

    // Fold copy 1 into copy 0, then tree-reduce 256 columns x 10 bins.
#pragma unroll
    for (int b = 0; b < BINS; b++) {
        float2 a = hist[0][b][tid];
        float2 c = hist[1][b][tid];
        hist[0][b][tid] = make_float2(a.x + c.x, a.y + c.y);
    }
    __syncthreads();
    for (int off = TPB / 2; off > 0; off >>= 1) {
        if (tid < off) {
#pragma unroll
            for (int b = 0; b < BINS; b++) {
                float2 a = hist[0][b][tid];
                float2 c = hist[0][b][tid + off];
                hist[0][b][tid] = make_float2(a.x + c.x, a.y + c.y);
            }
        }
        __syncthreads();
    }

    if (tid < BINS) {
        atomicAdd(&g_cnt[tid], (double)hist[0][tid][0].x);
        atomicAdd(&g_sum[tid], (double)hist[0][tid][0].y);
    }
    __syncthreads();

    // Last-block finalize (and reset for the next graph replay).
    if (tid == 0) {
        __threadfence();
        unsigned old = atomicAdd(&g_done, 1u);
        s_last = (old == GRID - 1) ? 1 : 0;
    }
    __syncthreads();

    if (s_last && tid == 0) {
        __threadfence();
        volatile double* vc = g_cnt;
        volatile double* vs = g_sum;
        double cnt[BINS], sum[BINS];
        double nonempty = 0.0;
        for (int b = 0; b < BINS; b++) {
            cnt[b] = vc[b];
            sum[b] = vs[b];
            if (cnt[b] > 0.0) nonempty += 1.0;
        }
        // mean(weight*bce) = (1/N) * sum_b (N/gd_b) * S_b = sum_b S_b / gd_b
        double loss = 0.0;
        for (int b = 0; b < BINS; b++) {
            double gd = cnt[b] * nonempty;
            if (gd < 1e-4) gd = 1e-4;
            loss += sum[b] / gd;
        }
        out[0] = (float)loss;
        for (int b = 0; b < BINS; b++) { vc[b] = 0.0; vs[b] = 0.0; }
        __threadfence();
        g_done = 0u;
    }
}

extern "C" void kernel_launch(void* const* d_in, const int* in_sizes, int n_in,
                              void* d_out, int out_size)
{
    // x: [B,2] float32 (2B elems), target: [B] int32 (B elems) — identify by count.
    const float* x;
    const int*   t;
    int nrows;
    if (in_sizes[0] >= 2 * in_sizes[1]) {
        x = (const float*)d_in[0];
        t = (const int*)d_in[1];
        nrows = in_sizes[1];
    } else {
        x = (const float*)d_in[1];
        t = (const int*)d_in[0];
        nrows = in_sizes[0];
    }
    int nquads = nrows >> 2;

    ghm_fused<<<GRID, TPB>>>((const float4*)x, (const int4*)t, nquads, nrows,
                             x, t, (float*)d_out);
}

// round 7
// speedup vs baseline: 1.0645x; 1.0502x over previous
#include <cuda_runtime.h>

#define BINS 10
#define TPB  256
#define BPSM 4
#define GRID (152 * BPSM)   // one wave on GB300 (152 SMs)

// Global scratch (allocation-free __device__ globals, zero-init at load;
// last block re-zeros them each run so graph replays stay deterministic).
__device__ double       g_cnt[BINS];
__device__ double       g_sum[BINS];
__device__ unsigned int g_done;

__device__ __forceinline__ float rcp_fast(float x) { float r; asm("rcp.approx.f32 %0, %1;" : "=f"(r) : "f"(x)); return r; }
__device__ __forceinline__ float lg2_fast(float x) { float r; asm("lg2.approx.f32 %0, %1;" : "=f"(r) : "f"(x)); return r; }
__device__ __forceinline__ float ex2_fast(float x) { float r; asm("ex2.approx.f32 %0, %1;" : "=f"(r) : "f"(x)); return r; }

__device__ __forceinline__ unsigned smem_off(const void* p)
{
    unsigned a;
    asm("{ .reg .u64 t; cvta.to.shared.u64 t, %1; cvt.u32.u64 %0, t; }"
        : "=r"(a) : "l"(p));
    return a;
}

// One element, pinned at PTX level (18 ops):
//   s = x ^ mask  (mask = target-match << 31);  |s| = |x|
//   e = exp(-|x|);  d = 1+e;  u = 9.9999 * rcp(d)
//   us = (s>=0) ? u : 9.9999-u;  bin = trunc(us)  (in [0,9] by construction)
//   bce = (s>=0 ? |x| : 0) + ln2 * lg2(d)
//   hist RMW: float2 at hoff + bin*2048 (bank = tid: conflict-free)
// Constants: 0fBFB8AA3B = -log2(e), 0f411FFF97 = 9.9999f, 0f3F317218 = ln(2)
#define GHM_ELEM(xval, msk, hoff)                                        \
    asm volatile(                                                        \
        "{\n\t"                                                          \
        ".reg .f32 ax,w,e,d,r,u,v,us,m,lg,b,h0,h1;\n\t"                  \
        ".reg .pred p;\n\t"                                              \
        ".reg .b32 sx,bin,off;\n\t"                                      \
        "xor.b32 sx, %0, %1;\n\t"                                        \
        "abs.f32 ax, %2;\n\t"                                            \
        "mul.f32 w, ax, 0fBFB8AA3B;\n\t"                                 \
        "ex2.approx.f32 e, w;\n\t"                                       \
        "add.f32 d, e, 0f3F800000;\n\t"                                  \
        "rcp.approx.f32 r, d;\n\t"                                       \
        "mul.f32 u, r, 0f411FFF97;\n\t"                                  \
        "sub.f32 v, 0f411FFF97, u;\n\t"                                  \
        "setp.ge.s32 p, sx, 0;\n\t"                                      \
        "selp.f32 us, u, v, p;\n\t"                                      \
        "cvt.rzi.s32.f32 bin, us;\n\t"                                   \
        "selp.f32 m, ax, 0f00000000, p;\n\t"                             \
        "lg2.approx.f32 lg, d;\n\t"                                      \
        "fma.rn.f32 b, lg, 0f3F317218, m;\n\t"                           \
        "mad.lo.s32 off, bin, 2048, %3;\n\t"                             \
        "ld.shared.v2.f32 {h0,h1}, [off];\n\t"                           \
        "add.f32 h0, h0, 0f3F800000;\n\t"                                \
        "add.f32 h1, h1, b;\n\t"                                         \
        "st.shared.v2.f32 [off], {h0,h1};\n\t"                           \
        "}\n\t"                                                          \
        :: "r"(__float_as_int(xval)), "r"(msk), "f"(xval), "r"(hoff))

__global__ void __launch_bounds__(TPB, BPSM)
ghm_fused(const float4* __restrict__ x4,
          const int4*   __restrict__ t4,
          int nquads, int nrows,
          const float* __restrict__ xs,
          const int*   __restrict__ ts,
          float* __restrict__ out)
{
    // Two privatized histograms (even/odd element slots) -> two independent
    // smem RMW chains. hist[c][bin][tid], float2 = (count, bce_sum).
    __shared__ float2 hist[2][BINS][TPB];
    __shared__ int    s_last;
    const int tid = threadIdx.x;
#pragma unroll
    for (int b = 0; b < BINS; b++) {
        hist[0][b][tid] = make_float2(0.0f, 0.0f);
        hist[1][b][tid] = make_float2(0.0f, 0.0f);
    }
    __syncthreads();

    const unsigned h0 = smem_off(&hist[0][0][tid]);
    const unsigned h1 = h0 + BINS * TPB * 8;    // hist[1], same tid column

    // 2-deep software pipeline: prefetch iteration i+1's 48 bytes into
    // registers while the element bodies for iteration i execute.
    const int stride = GRID * TPB;
    int i = blockIdx.x * TPB + tid;
    bool valid = (i < nquads);
    float4 xa, xb; int4 tv;
    if (valid) {
        xa = __ldcs(&x4[2 * i]);
        xb = __ldcs(&x4[2 * i + 1]);
        tv = __ldcs(&t4[i]);
    }
    while (valid) {
        int inext = i + stride;
        bool vnext = (inext < nquads);
        float4 nxa, nxb; int4 ntv;
        if (vnext) {
            nxa = __ldcs(&x4[2 * inext]);
            nxb = __ldcs(&x4[2 * inext + 1]);
            ntv = __ldcs(&t4[inext]);
        }

        // Row sign masks: class1 mask = t<<31, class0 mask = that ^ signbit.
        unsigned ma1 = ((unsigned)tv.x) << 31, ma0 = ma1 ^ 0x80000000u;
        unsigned mb1 = ((unsigned)tv.y) << 31, mb0 = mb1 ^ 0x80000000u;
        unsigned mc1 = ((unsigned)tv.z) << 31, mc0 = mc1 ^ 0x80000000u;
        unsigned md1 = ((unsigned)tv.w) << 31, md0 = md1 ^ 0x80000000u;

        GHM_ELEM(xa.x, ma0, h0);
        GHM_ELEM(xa.y, ma1, h1);
        GHM_ELEM(xa.z, mb0, h0);
        GHM_ELEM(xa.w, mb1, h1);
        GHM_ELEM(xb.x, mc0, h0);
        GHM_ELEM(xb.y, mc1, h1);
        GHM_ELEM(xb.z, md0, h0);
        GHM_ELEM(xb.w, md1, h1);

        xa = nxa; xb = nxb; tv = ntv;
        i = inext; valid = vnext;
    }

    // Tail rows (nrows % 4 != 0): direct double atomics, block 0 only.
    if (blockIdx.x == 0) {
        int tail0 = nquads * 4;
        for (int rowi = tail0 + tid; rowi < nrows; rowi += TPB) {
            int t = ts[rowi];
            for (int c = 0; c < 2; c++) {
                float x = xs[rowi * 2 + c];
                unsigned mask = ((t == c) ? 0x80000000u : 0u);
                int   sx = __float_as_int(x) ^ (int)mask;
                float ax = fabsf(x);
                float e  = ex2_fast(ax * -1.4426950408889634f);
                float d  = 1.0f + e;
                float u  = rcp_fast(d) * 9.9999f;
                bool pos = (sx >= 0);
                float us = pos ? u : (9.9999f - u);
                int  bin = (int)us;
                float m  = pos ? ax : 0.0f;
                float bce = fmaf(lg2_fast(d), 0.69314718055994531f, m);
                atomicAdd(&g_cnt[bin], 1.0);
                atomicAdd(&g_sum[bin], (double)bce);
            }
        }
    }
    __syncthreads();

    // Fold copy 1 into copy 0, then tree-reduce 256 columns x 10 bins.
#pragma unroll
    for (int b = 0; b < BINS; b++) {
        float2 a = hist[0][b][tid];
        float2 c = hist[1][b][tid];
        hist[0][b][tid] = make_float2(a.x + c.x, a.y + c.y);
    }
    __syncthreads();
    for (int off = TPB / 2; off > 0; off >>= 1) {
        if (tid < off) {
#pragma unroll
            for (int b = 0; b < BINS; b++) {
                float2 a = hist[0][b][tid];
                float2 c = hist[0][b][tid + off];
                hist[0][b][tid] = make_float2(a.x + c.x, a.y + c.y);
            }
        }
        __syncthreads();
    }

    if (tid < BINS) {
        atomicAdd(&g_cnt[tid], (double)hist[0][tid][0].x);
        atomicAdd(&g_sum[tid], (double)hist[0][tid][0].y);
    }
    __syncthreads();

    // Last-block finalize (and reset for the next graph replay).
    if (tid == 0) {
        __threadfence();
        unsigned old = atomicAdd(&g_done, 1u);
        s_last = (old == GRID - 1) ? 1 : 0;
    }
    __syncthreads();

    if (s_last && tid == 0) {
        __threadfence();
        volatile double* vc = g_cnt;
        volatile double* vs = g_sum;
        double cnt[BINS], sum[BINS];
        double nonempty = 0.0;
        for (int b = 0; b < BINS; b++) {
            cnt[b] = vc[b];
            sum[b] = vs[b];
            if (cnt[b] > 0.0) nonempty += 1.0;
        }
        // mean(weight*bce) = (1/N) * sum_b (N/gd_b) * S_b = sum_b S_b / gd_b
        double loss = 0.0;
        for (int b = 0; b < BINS; b++) {
            double gd = cnt[b] * nonempty;
            if (gd < 1e-4) gd = 1e-4;
            loss += sum[b] / gd;
        }
        out[0] = (float)loss;
        for (int b = 0; b < BINS; b++) { vc[b] = 0.0; vs[b] = 0.0; }
        __threadfence();
        g_done = 0u;
    }
}

extern "C" void kernel_launch(void* const* d_in, const int* in_sizes, int n_in,
                              void* d_out, int out_size)
{
    // x: [B,2] float32 (2B elems), target: [B] int32 (B elems) — identify by count.
    const float* x;
    const int*   t;
    int nrows;
    if (in_sizes[0] >= 2 * in_sizes[1]) {
        x = (const float*)d_in[0];
        t = (const int*)d_in[1];
        nrows = in_sizes[1];
    } else {
        x = (const float*)d_in[1];
        t = (const int*)d_in[0];
        nrows = in_sizes[0];
    }
    int nquads = nrows >> 2;

    ghm_fused<<<GRID, TPB>>>((const float4*)x, (const int4*)t, nquads, nrows,
                             x, t, (float*)d_out);
}